// round 14
// baseline (speedup 1.0000x reference)
#include <cuda_runtime.h>
#include <cuda_bf16.h>

#define NP 512

// single-instruction approx reciprocal (MUFU.RCP, ~1ulp)
__device__ __forceinline__ float frcp(float x) {
    float r; asm("rcp.approx.f32 %0,%1;" : "=f"(r) : "f"(x)); return r;
}

// One block per batch element; 512 threads. Plain scalar diff-form math,
// scalar float SoA in smem (LDS.32, 2-phase, conflict-free).
//
// Thread t: i = t & 255, h = t >> 8. Owns FOUR particles:
//   A = i, B = i+256, C = i+128, D = i+384   (registers)
// For k in [129+64h, 192+64h], one 6-float load (entries j = i+k, j+256)
// feeds FOUR pairs: (A,j) offset k, (B,j+256) offset k,
//                   (C,j) offset k-128, (D,j+256) offset k-128.
// Offsets 1..255 hit every unordered pair exactly once; offset 256 (h=1
// tail, A/B side) hits distance-256 pairs twice -> weight 1/2.
// Total LJ = 2 * sum.
//
// KEY CHANGE vs R11: the 63-trip loop is FULLY unrolled, so every smem
// index is base + literal. ptxas computes one base register per array and
// issues LDS [R+imm] — eliminating the per-iteration IADD address chain
// that consumed ~25% of issue slots (alu pipe) in R11/R13.
__global__ __launch_bounds__(NP, 1)
void lj_osc_kernel(const float* __restrict__ x, float* __restrict__ out) {
    __shared__ float xs[NP + 256];
    __shared__ float ys[NP + 256];
    __shared__ float zs[NP + 256];
    __shared__ float red[5][16];

    const int b = blockIdx.x;
    const int t = threadIdx.x;
    const int i = t & 255;
    const int h = t >> 8;
    const float* __restrict__ xb = x + (size_t)b * (NP * 3);

    // Coalesced load of 1536 floats; scatter into scalar SoA (+256 duplicate).
    {
        float v0 = xb[t];
        float v1 = xb[t + 512];
        float v2 = xb[t + 1024];
        int e, p, d;
#define SCATTER(VAL, EE) {                                              \
        e = (EE); p = e / 3; d = e - 3 * p;                             \
        float* a = (d == 0) ? xs : (d == 1) ? ys : zs;                  \
        a[p] = VAL;                                                     \
        if (p < 256) a[p + NP] = VAL; }
        SCATTER(v0, t)
        SCATTER(v1, t + 512)
        SCATTER(v2, t + 1024)
#undef SCATTER
    }
    __syncthreads();

    // Own 4 particles in registers.
    const float axA = xs[i],       ayA = ys[i],       azA = zs[i];
    const float axB = xs[i + 256], ayB = ys[i + 256], azB = zs[i + 256];
    const float axC = xs[i + 128], ayC = ys[i + 128], azC = zs[i + 128];
    const float axD = xs[i + 384], ayD = ys[i + 384], azD = zs[i + 384];

    // 8 accumulators: (Sum r^-6, Sum r^-12) per owned particle.
    float s6A = 0.f, s12A = 0.f, s6B = 0.f, s12B = 0.f;
    float s6C = 0.f, s12C = 0.f, s6D = 0.f, s12D = 0.f;
    float tacc = 0.f;   // weighted tail

#define PAIR(AX, AY, AZ, JX, JY, JZ, S6, S12) {                          \
        float dx = (JX) - (AX);                                          \
        float dy = (JY) - (AY);                                          \
        float dz = (JZ) - (AZ);                                          \
        float s  = fmaf(dx, dx, fmaf(dy, dy, fmaf(dz, dz, 1e-6f)));      \
        float r  = frcp(s);                                              \
        float r3 = r * r * r;                                            \
        S6 += r3;                                                        \
        S12 = fmaf(r3, r3, S12); }

    const int base = i + 129 + (h << 6);   // i+129 (h=0) or i+193 (h=1)

    // FULL unroll: all 63 regular QUADs use literal offsets from `base`.
    #pragma unroll
    for (int m = 0; m < 63; ++m) {
        float xj  = xs[base + m],       yj  = ys[base + m],       zj  = zs[base + m];
        float xj2 = xs[base + m + 256], yj2 = ys[base + m + 256], zj2 = zs[base + m + 256];
        PAIR(axA, ayA, azA, xj,  yj,  zj,  s6A, s12A)
        PAIR(axB, ayB, azB, xj2, yj2, zj2, s6B, s12B)
        PAIR(axC, ayC, azC, xj,  yj,  zj,  s6C, s12C)
        PAIR(axD, ayD, azD, xj2, yj2, zj2, s6D, s12D)
    }
    // Tail m = 63: k = 192 (h=0, weight 1) or k = 256 (h=1, A/B weight 1/2).
    {
        float xj  = xs[base + 63],       yj  = ys[base + 63],       zj  = zs[base + 63];
        float xj2 = xs[base + 63 + 256], yj2 = ys[base + 63 + 256], zj2 = zs[base + 63 + 256];
        float w = h ? 0.5f : 1.0f;
        {   // A side, weighted
            float dx = xj - axA, dy = yj - ayA, dz = zj - azA;
            float s  = fmaf(dx, dx, fmaf(dy, dy, fmaf(dz, dz, 1e-6f)));
            float r  = frcp(s);
            float r3 = r * r * r;
            tacc = fmaf(w, fmaf(r3, r3 - 2.0f, 0.f), tacc);
        }
        {   // B side, weighted
            float dx = xj2 - axB, dy = yj2 - ayB, dz = zj2 - azB;
            float s  = fmaf(dx, dx, fmaf(dy, dy, fmaf(dz, dz, 1e-6f)));
            float r  = frcp(s);
            float r3 = r * r * r;
            tacc = fmaf(w, fmaf(r3, r3 - 2.0f, 0.f), tacc);
        }
        PAIR(axC, ayC, azC, xj,  yj,  zj,  s6C, s12C)
        PAIR(axD, ayD, azD, xj2, yj2, zj2, s6D, s12D)
    }
#undef PAIR

    float sum6  = (s6A + s6B) + (s6C + s6D);
    float sum12 = (s12A + s12B) + (s12C + s12D);
    float acc = fmaf(-2.0f, sum6, sum12) + tacc;

    // Oscillator terms: h=0 threads contribute particles A and B
    // (i and i+256) -> each particle exactly once.
    float sx = 0.f, sy = 0.f, sz = 0.f, ssq = 0.f;
    if (h == 0) {
        sx = axA + axB;
        sy = ayA + ayB;
        sz = azA + azB;
        ssq = fmaf(axA, axA, fmaf(ayA, ayA, azA * azA))
            + fmaf(axB, axB, fmaf(ayB, ayB, azB * azB));
    }

    // Block reduction of 5 values: acc(LJ), sum_x, sum_y, sum_z, sum_sq
    float v[5] = {acc, sx, sy, sz, ssq};
    const unsigned FULL = 0xFFFFFFFFu;
    #pragma unroll
    for (int q = 0; q < 5; ++q) {
        float r = v[q];
        r += __shfl_down_sync(FULL, r, 16);
        r += __shfl_down_sync(FULL, r, 8);
        r += __shfl_down_sync(FULL, r, 4);
        r += __shfl_down_sync(FULL, r, 2);
        r += __shfl_down_sync(FULL, r, 1);
        v[q] = r;
    }
    const int warp = t >> 5;
    const int lane = t & 31;
    if (lane == 0) {
        #pragma unroll
        for (int q = 0; q < 5; ++q) red[q][warp] = v[q];
    }
    __syncthreads();
    if (warp == 0) {
        float r[5];
        #pragma unroll
        for (int q = 0; q < 5; ++q) {
            float val = (lane < 16) ? red[q][lane] : 0.0f;
            val += __shfl_down_sync(FULL, val, 8);
            val += __shfl_down_sync(FULL, val, 4);
            val += __shfl_down_sync(FULL, val, 2);
            val += __shfl_down_sync(FULL, val, 1);
            r[q] = val;
        }
        if (lane == 0) {
            float lj_total = 2.0f * r[0];
            float mean_sq = (r[1] * r[1] + r[2] * r[2] + r[3] * r[3]) * (1.0f / NP);
            float osc = 0.5f * (r[4] - mean_sq);
            out[b] = lj_total + osc;
        }
    }
}

extern "C" void kernel_launch(void* const* d_in, const int* in_sizes, int n_in,
                              void* d_out, int out_size) {
    const float* x = (const float*)d_in[0];
    float* out = (float*)d_out;
    int batches = in_sizes[0] / (NP * 3);   // 128
    lj_osc_kernel<<<batches, NP>>>(x, out);
}

// round 15
// speedup vs baseline: 1.4886x; 1.4886x over previous
#include <cuda_runtime.h>
#include <cuda_bf16.h>

#define NP 512

// single-instruction approx reciprocal (MUFU.RCP, ~1ulp)
__device__ __forceinline__ float frcp(float x) {
    float r; asm("rcp.approx.f32 %0,%1;" : "=f"(r) : "f"(x)); return r;
}

// One block per batch element; 512 threads. Plain scalar diff-form math,
// scalar float SoA in smem (LDS.32, 2-phase, conflict-free).
//
// Thread t: i = t & 255, h = t >> 8. Owns FOUR particles:
//   A = i, B = i+256, C = i+128, D = i+384   (registers)
// For k in [129+64h, 192+64h], one 6-float load (entries j = i+k, j+256)
// feeds FOUR pairs: (A,j) offset k, (B,j+256) offset k,
//                   (C,j) offset k-128, (D,j+256) offset k-128.
// Offsets 1..255 hit every unordered pair exactly once; offset 256 (h=1
// tail, A/B side) hits distance-256 pairs twice -> weight 1/2.
// Total LJ = 2 * sum.
//
// KEY CHANGE vs R11: the 63-trip loop is FULLY unrolled, so every smem
// index is base + literal. ptxas computes one base register per array and
// issues LDS [R+imm] — eliminating the per-iteration IADD address chain
// that consumed ~25% of issue slots (alu pipe) in R11/R13.
__global__ __launch_bounds__(NP, 1)
void lj_osc_kernel(const float* __restrict__ x, float* __restrict__ out) {
    __shared__ float xs[NP + 256];
    __shared__ float ys[NP + 256];
    __shared__ float zs[NP + 256];
    __shared__ float red[5][16];

    const int b = blockIdx.x;
    const int t = threadIdx.x;
    const int i = t & 255;
    const int h = t >> 8;
    const float* __restrict__ xb = x + (size_t)b * (NP * 3);

    // Coalesced load of 1536 floats; scatter into scalar SoA (+256 duplicate).
    {
        float v0 = xb[t];
        float v1 = xb[t + 512];
        float v2 = xb[t + 1024];
        int e, p, d;
#define SCATTER(VAL, EE) {                                              \
        e = (EE); p = e / 3; d = e - 3 * p;                             \
        float* a = (d == 0) ? xs : (d == 1) ? ys : zs;                  \
        a[p] = VAL;                                                     \
        if (p < 256) a[p + NP] = VAL; }
        SCATTER(v0, t)
        SCATTER(v1, t + 512)
        SCATTER(v2, t + 1024)
#undef SCATTER
    }
    __syncthreads();

    // Own 4 particles in registers.
    const float axA = xs[i],       ayA = ys[i],       azA = zs[i];
    const float axB = xs[i + 256], ayB = ys[i + 256], azB = zs[i + 256];
    const float axC = xs[i + 128], ayC = ys[i + 128], azC = zs[i + 128];
    const float axD = xs[i + 384], ayD = ys[i + 384], azD = zs[i + 384];

    // 8 accumulators: (Sum r^-6, Sum r^-12) per owned particle.
    float s6A = 0.f, s12A = 0.f, s6B = 0.f, s12B = 0.f;
    float s6C = 0.f, s12C = 0.f, s6D = 0.f, s12D = 0.f;
    float tacc = 0.f;   // weighted tail

#define PAIR(AX, AY, AZ, JX, JY, JZ, S6, S12) {                          \
        float dx = (JX) - (AX);                                          \
        float dy = (JY) - (AY);                                          \
        float dz = (JZ) - (AZ);                                          \
        float s  = fmaf(dx, dx, fmaf(dy, dy, fmaf(dz, dz, 1e-6f)));      \
        float r  = frcp(s);                                              \
        float r3 = r * r * r;                                            \
        S6 += r3;                                                        \
        S12 = fmaf(r3, r3, S12); }

    const int base = i + 129 + (h << 6);   // i+129 (h=0) or i+193 (h=1)

    // FULL unroll: all 63 regular QUADs use literal offsets from `base`.
    #pragma unroll
    for (int m = 0; m < 63; ++m) {
        float xj  = xs[base + m],       yj  = ys[base + m],       zj  = zs[base + m];
        float xj2 = xs[base + m + 256], yj2 = ys[base + m + 256], zj2 = zs[base + m + 256];
        PAIR(axA, ayA, azA, xj,  yj,  zj,  s6A, s12A)
        PAIR(axB, ayB, azB, xj2, yj2, zj2, s6B, s12B)
        PAIR(axC, ayC, azC, xj,  yj,  zj,  s6C, s12C)
        PAIR(axD, ayD, azD, xj2, yj2, zj2, s6D, s12D)
    }
    // Tail m = 63: k = 192 (h=0, weight 1) or k = 256 (h=1, A/B weight 1/2).
    {
        float xj  = xs[base + 63],       yj  = ys[base + 63],       zj  = zs[base + 63];
        float xj2 = xs[base + 63 + 256], yj2 = ys[base + 63 + 256], zj2 = zs[base + 63 + 256];
        float w = h ? 0.5f : 1.0f;
        {   // A side, weighted
            float dx = xj - axA, dy = yj - ayA, dz = zj - azA;
            float s  = fmaf(dx, dx, fmaf(dy, dy, fmaf(dz, dz, 1e-6f)));
            float r  = frcp(s);
            float r3 = r * r * r;
            tacc = fmaf(w, fmaf(r3, r3 - 2.0f, 0.f), tacc);
        }
        {   // B side, weighted
            float dx = xj2 - axB, dy = yj2 - ayB, dz = zj2 - azB;
            float s  = fmaf(dx, dx, fmaf(dy, dy, fmaf(dz, dz, 1e-6f)));
            float r  = frcp(s);
            float r3 = r * r * r;
            tacc = fmaf(w, fmaf(r3, r3 - 2.0f, 0.f), tacc);
        }
        PAIR(axC, ayC, azC, xj,  yj,  zj,  s6C, s12C)
        PAIR(axD, ayD, azD, xj2, yj2, zj2, s6D, s12D)
    }
#undef PAIR

    float sum6  = (s6A + s6B) + (s6C + s6D);
    float sum12 = (s12A + s12B) + (s12C + s12D);
    float acc = fmaf(-2.0f, sum6, sum12) + tacc;

    // Oscillator terms: h=0 threads contribute particles A and B
    // (i and i+256) -> each particle exactly once.
    float sx = 0.f, sy = 0.f, sz = 0.f, ssq = 0.f;
    if (h == 0) {
        sx = axA + axB;
        sy = ayA + ayB;
        sz = azA + azB;
        ssq = fmaf(axA, axA, fmaf(ayA, ayA, azA * azA))
            + fmaf(axB, axB, fmaf(ayB, ayB, azB * azB));
    }

    // Block reduction of 5 values: acc(LJ), sum_x, sum_y, sum_z, sum_sq
    float v[5] = {acc, sx, sy, sz, ssq};
    const unsigned FULL = 0xFFFFFFFFu;
    #pragma unroll
    for (int q = 0; q < 5; ++q) {
        float r = v[q];
        r += __shfl_down_sync(FULL, r, 16);
        r += __shfl_down_sync(FULL, r, 8);
        r += __shfl_down_sync(FULL, r, 4);
        r += __shfl_down_sync(FULL, r, 2);
        r += __shfl_down_sync(FULL, r, 1);
        v[q] = r;
    }
    const int warp = t >> 5;
    const int lane = t & 31;
    if (lane == 0) {
        #pragma unroll
        for (int q = 0; q < 5; ++q) red[q][warp] = v[q];
    }
    __syncthreads();
    if (warp == 0) {
        float r[5];
        #pragma unroll
        for (int q = 0; q < 5; ++q) {
            float val = (lane < 16) ? red[q][lane] : 0.0f;
            val += __shfl_down_sync(FULL, val, 8);
            val += __shfl_down_sync(FULL, val, 4);
            val += __shfl_down_sync(FULL, val, 2);
            val += __shfl_down_sync(FULL, val, 1);
            r[q] = val;
        }
        if (lane == 0) {
            float lj_total = 2.0f * r[0];
            float mean_sq = (r[1] * r[1] + r[2] * r[2] + r[3] * r[3]) * (1.0f / NP);
            float osc = 0.5f * (r[4] - mean_sq);
            out[b] = lj_total + osc;
        }
    }
}

extern "C" void kernel_launch(void* const* d_in, const int* in_sizes, int n_in,
                              void* d_out, int out_size) {
    const float* x = (const float*)d_in[0];
    float* out = (float*)d_out;
    int batches = in_sizes[0] / (NP * 3);   // 128
    lj_osc_kernel<<<batches, NP>>>(x, out);
}